// round 7
// baseline (speedup 1.0000x reference)
#include <cuda_runtime.h>
#include <cuda_bf16.h>
#include <stdint.h>

#define HID  128
#define OBS  64

// pre-packed MMA B-fragments, uint4 = {b0_hi, b1_hi, b0_lo, b1_lo}
// g_Bemb[(kt*16+j)*32+lane], kt 0..3
__device__ __align__(16) uint4 g_Bemb[2048];
// g_Wf[l*4096 + (kt*16+j)*32+lane], kt 0..7
__device__ __align__(16) uint4 g_Wf[8192];

__device__ __forceinline__ uint32_t bf16_hi_bits(float v) {
    return (uint32_t)__bfloat16_as_ushort(__float2bfloat16(v));
}
__device__ __forceinline__ uint32_t cvt_bf16x2(float hi_elt, float lo_elt) {
    uint32_t r;
    asm("cvt.rn.bf16x2.f32 %0, %1, %2;" : "=r"(r) : "f"(hi_elt), "f"(lo_elt));
    return r;   // [31:16]=bf16(hi_elt), [15:0]=bf16(lo_elt)
}
__device__ __forceinline__ float lo_f(uint32_t u) { return __uint_as_float(u << 16); }
__device__ __forceinline__ float hi_f(uint32_t u) { return __uint_as_float(u & 0xffff0000u); }
__device__ __forceinline__ float htanh(float x) {
    float y; asm("tanh.approx.f32 %0, %1;" : "=f"(y) : "f"(x)); return y;
}
__device__ __forceinline__ void mma_bf16(float& c0, float& c1, float& c2, float& c3,
                                         uint32_t a0, uint32_t a1, uint32_t a2, uint32_t a3,
                                         uint32_t b0, uint32_t b1) {
    asm volatile(
        "mma.sync.aligned.m16n8k16.row.col.f32.bf16.bf16.f32 "
        "{%0,%1,%2,%3}, {%4,%5,%6,%7}, {%8,%9}, {%0,%1,%2,%3};"
        : "+f"(c0), "+f"(c1), "+f"(c2), "+f"(c3)
        : "r"(a0), "r"(a1), "r"(a2), "r"(a3), "r"(b0), "r"(b1));
}

// ---- prep: pack w_emb / w_gcn into uint4 B-fragments (hi/lo split bf16) ----
__global__ void prep_kernel(const float* __restrict__ w_emb,
                            const float* __restrict__ w_gcn) {
    if (blockIdx.x < 16) {
        int idx  = blockIdx.x * 128 + threadIdx.x;   // 0..2047
        int lane = idx & 31;
        int j    = (idx >> 5) & 15;
        int kt   = idx >> 9;                          // 0..3
        int g    = lane >> 2, tid = lane & 3;
        int n    = j * 8 + g;
        uint32_t hv[2], lv[2];
        #pragma unroll
        for (int p = 0; p < 2; p++) {
            int k0 = kt * 16 + tid * 2 + p * 8;
            float v0 = w_emb[k0 * HID + n];
            float v1 = w_emb[(k0 + 1) * HID + n];
            uint32_t h0 = bf16_hi_bits(v0), h1 = bf16_hi_bits(v1);
            uint32_t l0 = bf16_hi_bits(v0 - __uint_as_float(h0 << 16));
            uint32_t l1 = bf16_hi_bits(v1 - __uint_as_float(h1 << 16));
            hv[p] = (h1 << 16) | h0;
            lv[p] = (l1 << 16) | l0;
        }
        g_Bemb[(kt * 16 + j) * 32 + lane] = make_uint4(hv[0], hv[1], lv[0], lv[1]);
    } else {
        int idx  = (blockIdx.x - 16) * 128 + threadIdx.x;   // 0..8191
        int lane = idx & 31;
        int j    = (idx >> 5) & 15;
        int kt   = (idx >> 9) & 7;                          // 0..7
        int l    = idx >> 12;                               // 0..1
        int g    = lane >> 2, tid = lane & 3;
        int n    = j * 8 + g;
        uint32_t hv[2], lv[2];
        #pragma unroll
        for (int p = 0; p < 2; p++) {
            int k0 = kt * 16 + tid * 2 + p * 8;
            float v0 = w_gcn[l * HID * HID + k0 * HID + n];
            float v1 = w_gcn[l * HID * HID + (k0 + 1) * HID + n];
            uint32_t h0 = bf16_hi_bits(v0), h1 = bf16_hi_bits(v1);
            uint32_t l0 = bf16_hi_bits(v0 - __uint_as_float(h0 << 16));
            uint32_t l1 = bf16_hi_bits(v1 - __uint_as_float(h1 << 16));
            hv[p] = (h1 << 16) | h0;
            lv[p] = (l1 << 16) | l0;
        }
        g_Wf[l * 4096 + (kt * 16 + j) * 32 + lane] = make_uint4(hv[0], hv[1], lv[0], lv[1]);
    }
}

// block = 128 thr = 4 warps = 2 graphs x 2 col-halves
// warp w: graph gr = w>>1 (local 0/1), col-half jh = w&1 (j-tiles jh*8..jh*8+7)
// smem: s_xp[8][68] u32  (rows 0-1: hi-xbar graphs 0-1, rows 4-5: lo-xbar; 2,3,6,7 zero)
//       s_m [2][136] f32 ; s_red[4]
__global__ __launch_bounds__(128, 4)
void gcn_critic_kernel(const float* __restrict__ cent_obs,
                       const float* __restrict__ b_emb,
                       const float* __restrict__ b_gcn,
                       const float* __restrict__ w_fc1,
                       const float* __restrict__ b_fc1,
                       float* __restrict__ out)
{
    __shared__ uint32_t s_xp[8 * 68];
    __shared__ float    s_m[2 * 136];
    __shared__ float    s_red[4];

    const int t    = threadIdx.x;
    const int w    = t >> 5;
    const int lane = t & 31;
    const int g    = lane >> 2;
    const int tid  = lane & 3;
    const int gr   = w >> 1;          // local graph 0..1
    const int jh   = w & 1;           // col-half 0..1

    // zero the unused A rows (2,3,6,7) of s_xp once
    if (t < 136) {
        s_xp[2 * 68 + t] = 0u;        // rows 2,3
        s_xp[6 * 68 + t] = 0u;        // rows 6,7
    }

    const long n0 = (long)blockIdx.x * 32 + gr * 16 + g;
    const long n1 = n0 + 8;

    // ---- A fragments for embedding, straight from obs (split bf16) ----
    uint32_t aH[16], aL[16];
    {
        const float* r0p = cent_obs + n0 * OBS;
        const float* r1p = cent_obs + n1 * OBS;
        #pragma unroll
        for (int kt = 0; kt < 4; kt++)
            #pragma unroll
            for (int q = 0; q < 2; q++) {
                const int k = kt * 16 + tid * 2 + q * 8;
                const int idx = kt * 4 + q * 2;
                float2 v0 = *(const float2*)(r0p + k);
                float2 v1 = *(const float2*)(r1p + k);
                uint32_t h0 = cvt_bf16x2(v0.y, v0.x);
                aH[idx] = h0;
                aL[idx] = cvt_bf16x2(v0.y - hi_f(h0), v0.x - lo_f(h0));
                uint32_t h1 = cvt_bf16x2(v1.y, v1.x);
                aH[idx + 1] = h1;
                aL[idx + 1] = cvt_bf16x2(v1.y - hi_f(h1), v1.x - lo_f(h1));
            }
    }

    // ---- embedding GEMM: this warp's 8 j-tiles only ----
    float xr0[16], xr1[16];
    #pragma unroll
    for (int jj = 0; jj < 8; jj++) {
        const int j = jh * 8 + jj;
        float c0 = 0.f, c1 = 0.f, c2 = 0.f, c3 = 0.f;
        #pragma unroll
        for (int kt = 0; kt < 4; kt++) {
            uint4 B = g_Bemb[(kt * 16 + j) * 32 + lane];
            uint32_t a0 = aH[kt*4+0], a1 = aH[kt*4+1], a2 = aH[kt*4+2], a3 = aH[kt*4+3];
            uint32_t e0 = aL[kt*4+0], e1 = aL[kt*4+1], e2 = aL[kt*4+2], e3 = aL[kt*4+3];
            mma_bf16(c0, c1, c2, c3, a0, a1, a2, a3, B.x, B.y);   // hiA*hiB
            mma_bf16(c0, c1, c2, c3, e0, e1, e2, e3, B.x, B.y);   // loA*hiB
            mma_bf16(c0, c1, c2, c3, a0, a1, a2, a3, B.z, B.w);   // hiA*loB
        }
        float2 be = *(const float2*)(b_emb + j * 8 + 2 * tid);
        xr0[2*jj]   = c0 + be.x; xr0[2*jj+1] = c1 + be.y;
        xr1[2*jj]   = c2 + be.x; xr1[2*jj+1] = c3 + be.y;
    }

    // ---- GCN layers (agg == per-graph mean: deg 16, norm 1/16) ----
    #pragma unroll
    for (int l = 0; l < 2; l++) {
        // xbar over this warp's 16 nodes; split hi/lo; lane g stores j-tile g
        {
            float s[16];
            #pragma unroll
            for (int c = 0; c < 16; c++) s[c] = xr0[c] + xr1[c];
            #pragma unroll
            for (int off = 4; off <= 16; off <<= 1)
                #pragma unroll
                for (int c = 0; c < 16; c++)
                    s[c] += __shfl_xor_sync(0xffffffffu, s[c], off);
            // lane (g, tid) stores cols of j-tile (jh*8+g), bf16x2-packed
            float v0 = s[2*g]   * 0.0625f;
            float v1 = s[2*g+1] * 0.0625f;
            uint32_t hp = cvt_bf16x2(v1, v0);
            uint32_t lp = cvt_bf16x2(v1 - hi_f(hp), v0 - lo_f(hp));
            const int ci = (jh * 8 + g) * 4 + tid;
            s_xp[gr * 68 + ci]       = hp;
            s_xp[(gr + 4) * 68 + ci] = lp;
        }
        __syncthreads();

        // matvec via HMMA: A rows 0-1 = hi-xbar, 4-5 = lo-xbar (2,3,6,7 zero)
        // warp w computes j-tiles w*4 .. w*4+3 for both graphs
        {
            float c1r[4][2], c2r[4][2];
            #pragma unroll
            for (int jj = 0; jj < 4; jj++) {
                c1r[jj][0] = c1r[jj][1] = 0.f;
                c2r[jj][0] = c2r[jj][1] = 0.f;
            }
            const uint4* WB = g_Wf + l * 4096;
            #pragma unroll
            for (int kt = 0; kt < 8; kt++) {
                uint32_t a0 = s_xp[g * 68 + 8 * kt + tid];
                uint32_t a2 = s_xp[g * 68 + 8 * kt + 4 + tid];
                uint32_t a0m = (g < 4) ? a0 : 0u;
                uint32_t a2m = (g < 4) ? a2 : 0u;
                #pragma unroll
                for (int jj = 0; jj < 4; jj++) {
                    const int j = w * 4 + jj;
                    uint4 B = WB[(kt * 16 + j) * 32 + lane];
                    float d2 = 0.f, d3 = 0.f;
                    mma_bf16(c1r[jj][0], c1r[jj][1], d2, d3,
                             a0, 0u, a2, 0u, B.x, B.y);     // hi & lo rows vs hiB
                    mma_bf16(c2r[jj][0], c2r[jj][1], d2, d3,
                             a0m, 0u, a2m, 0u, B.z, B.w);   // hi rows vs loB
                }
            }
            #pragma unroll
            for (int jj = 0; jj < 4; jj++) {
                float t0 = c1r[jj][0] + c2r[jj][0];
                float t1 = c1r[jj][1] + c2r[jj][1];
                t0 += __shfl_xor_sync(0xffffffffu, t0, 16);   // add lo rows
                t1 += __shfl_xor_sync(0xffffffffu, t1, 16);
                if (g < 2)
                    *(float2*)(s_m + g * 136 + 8 * (w * 4 + jj) + 2 * tid) =
                        make_float2(t0, t1);
            }
        }
        __syncthreads();

        // x = tanh(x + m[graph] + b_gcn)
        #pragma unroll
        for (int jj = 0; jj < 8; jj++) {
            const int j = jh * 8 + jj;
            float2 mg = *(const float2*)(s_m + gr * 136 + 8 * j + 2 * tid);
            float2 bg = *(const float2*)(b_gcn + l * HID + 8 * j + 2 * tid);
            const float a0 = mg.x + bg.x, a1 = mg.y + bg.y;
            xr0[2*jj]   = htanh(xr0[2*jj]   + a0);
            xr0[2*jj+1] = htanh(xr0[2*jj+1] + a1);
            xr1[2*jj]   = htanh(xr1[2*jj]   + a0);
            xr1[2*jj+1] = htanh(xr1[2*jj+1] + a1);
        }
        if (l == 0) __syncthreads();   // protect s_m/s_xp before next layer's writes
    }

    // ---- head: out[graph] = mean_{16 nodes}(x . w_fc1) + b ----
    {
        float p = 0.f;
        #pragma unroll
        for (int jj = 0; jj < 8; jj++) {
            const int j = jh * 8 + jj;
            float2 wf = *(const float2*)(w_fc1 + 8 * j + 2 * tid);
            p += (xr0[2*jj]   + xr1[2*jj])   * wf.x;
            p += (xr0[2*jj+1] + xr1[2*jj+1]) * wf.y;
        }
        #pragma unroll
        for (int off = 16; off; off >>= 1)
            p += __shfl_xor_sync(0xffffffffu, p, off);
        if (lane == 0) s_red[w] = p;
    }
    __syncthreads();
    if (t < 2)
        out[blockIdx.x * 2 + t] =
            (s_red[2 * t] + s_red[2 * t + 1]) * 0.0625f + b_fc1[0];
}

extern "C" void kernel_launch(void* const* d_in, const int* in_sizes, int n_in,
                              void* d_out, int out_size) {
    const float* cent_obs = (const float*)d_in[0];
    const float* w_emb    = (const float*)d_in[1];
    const float* b_emb    = (const float*)d_in[2];
    const float* w_gcn    = (const float*)d_in[3];
    const float* b_gcn    = (const float*)d_in[4];
    const float* w_fc1    = (const float*)d_in[5];
    const float* b_fc1    = (const float*)d_in[6];
    // edge_src/edge_dst: fixed complete graph -> per-graph mean; unused.
    float* out = (float*)d_out;

    prep_kernel<<<80, 128>>>(w_emb, w_gcn);

    const int blocks = out_size / 2;   // 4096
    gcn_critic_kernel<<<blocks, 128>>>(
        cent_obs, b_emb, b_gcn, w_fc1, b_fc1, out);
}

// round 8
// speedup vs baseline: 1.2028x; 1.2028x over previous
#include <cuda_runtime.h>
#include <cuda_bf16.h>
#include <stdint.h>

#define HID  128
#define OBS  64

// pre-packed MMA B-fragments, uint4 = {b0_hi, b1_hi, b0_lo, b1_lo}
// g_Bemb[(kt*16+j)*32+lane], kt 0..3
__device__ __align__(16) uint4 g_Bemb[2048];
// g_Wf[l*4096 + (kt*16+j)*32+lane], kt 0..7
__device__ __align__(16) uint4 g_Wf[8192];

__device__ __forceinline__ uint32_t bf16_hi_bits(float v) {
    return (uint32_t)__bfloat16_as_ushort(__float2bfloat16(v));
}
__device__ __forceinline__ uint32_t cvt_bf16x2(float hi_elt, float lo_elt) {
    uint32_t r;
    asm("cvt.rn.bf16x2.f32 %0, %1, %2;" : "=r"(r) : "f"(hi_elt), "f"(lo_elt));
    return r;   // [31:16]=bf16(hi_elt), [15:0]=bf16(lo_elt)
}
__device__ __forceinline__ float lo_f(uint32_t u) { return __uint_as_float(u << 16); }
__device__ __forceinline__ float hi_f(uint32_t u) { return __uint_as_float(u & 0xffff0000u); }
__device__ __forceinline__ float htanh(float x) {
    float y; asm("tanh.approx.f32 %0, %1;" : "=f"(y) : "f"(x)); return y;
}
__device__ __forceinline__ void mma_bf16(float& c0, float& c1, float& c2, float& c3,
                                         uint32_t a0, uint32_t a1, uint32_t a2, uint32_t a3,
                                         uint32_t b0, uint32_t b1) {
    asm volatile(
        "mma.sync.aligned.m16n8k16.row.col.f32.bf16.bf16.f32 "
        "{%0,%1,%2,%3}, {%4,%5,%6,%7}, {%8,%9}, {%0,%1,%2,%3};"
        : "+f"(c0), "+f"(c1), "+f"(c2), "+f"(c3)
        : "r"(a0), "r"(a1), "r"(a2), "r"(a3), "r"(b0), "r"(b1));
}

// ---- prep: pack w_emb / w_gcn into uint4 B-fragments (hi/lo split bf16) ----
__global__ void prep_kernel(const float* __restrict__ w_emb,
                            const float* __restrict__ w_gcn) {
    if (blockIdx.x < 16) {
        int idx  = blockIdx.x * 128 + threadIdx.x;   // 0..2047
        int lane = idx & 31;
        int j    = (idx >> 5) & 15;
        int kt   = idx >> 9;                          // 0..3
        int g    = lane >> 2, tid = lane & 3;
        int n    = j * 8 + g;
        uint32_t hv[2], lv[2];
        #pragma unroll
        for (int p = 0; p < 2; p++) {
            int k0 = kt * 16 + tid * 2 + p * 8;
            float v0 = w_emb[k0 * HID + n];
            float v1 = w_emb[(k0 + 1) * HID + n];
            uint32_t h0 = bf16_hi_bits(v0), h1 = bf16_hi_bits(v1);
            uint32_t l0 = bf16_hi_bits(v0 - __uint_as_float(h0 << 16));
            uint32_t l1 = bf16_hi_bits(v1 - __uint_as_float(h1 << 16));
            hv[p] = (h1 << 16) | h0;
            lv[p] = (l1 << 16) | l0;
        }
        g_Bemb[(kt * 16 + j) * 32 + lane] = make_uint4(hv[0], hv[1], lv[0], lv[1]);
    } else {
        int idx  = (blockIdx.x - 16) * 128 + threadIdx.x;   // 0..8191
        int lane = idx & 31;
        int j    = (idx >> 5) & 15;
        int kt   = (idx >> 9) & 7;                          // 0..7
        int l    = idx >> 12;                               // 0..1
        int g    = lane >> 2, tid = lane & 3;
        int n    = j * 8 + g;
        uint32_t hv[2], lv[2];
        #pragma unroll
        for (int p = 0; p < 2; p++) {
            int k0 = kt * 16 + tid * 2 + p * 8;
            float v0 = w_gcn[l * HID * HID + k0 * HID + n];
            float v1 = w_gcn[l * HID * HID + (k0 + 1) * HID + n];
            uint32_t h0 = bf16_hi_bits(v0), h1 = bf16_hi_bits(v1);
            uint32_t l0 = bf16_hi_bits(v0 - __uint_as_float(h0 << 16));
            uint32_t l1 = bf16_hi_bits(v1 - __uint_as_float(h1 << 16));
            hv[p] = (h1 << 16) | h0;
            lv[p] = (l1 << 16) | l0;
        }
        g_Wf[l * 4096 + (kt * 16 + j) * 32 + lane] = make_uint4(hv[0], hv[1], lv[0], lv[1]);
    }
}

// block = 128 thr = 4 warps = 4 graphs (warp == graph)
// smem: s_xp[8][68] u32 (rows 0-3 hi-xbar, rows 4-7 lo-xbar), s_m[4][136] f32
__global__ __launch_bounds__(128, 4)
void gcn_critic_kernel(const float* __restrict__ cent_obs,
                       const float* __restrict__ b_emb,
                       const float* __restrict__ b_gcn,
                       const float* __restrict__ w_fc1,
                       const float* __restrict__ b_fc1,
                       float* __restrict__ out)
{
    __shared__ uint32_t s_xp[8 * 68];
    __shared__ float    s_m[4 * 136];

    const int t    = threadIdx.x;
    const int w    = t >> 5;            // warp == local graph 0..3
    const int lane = t & 31;
    const int g    = lane >> 2;
    const int tid  = lane & 3;

    const long n0 = (long)blockIdx.x * 64 + w * 16 + g;
    const long n1 = n0 + 8;

    // ---- embedding GEMM, kt-outer to keep only one kt's A fragments live ----
    float xr0[32], xr1[32];
    {
        // init accumulators with bias
        #pragma unroll
        for (int j = 0; j < 16; j++) {
            float2 be = *(const float2*)(b_emb + 8 * j + 2 * tid);
            xr0[2*j] = be.x; xr0[2*j+1] = be.y;
            xr1[2*j] = be.x; xr1[2*j+1] = be.y;
        }
        const float* r0p = cent_obs + n0 * OBS;
        const float* r1p = cent_obs + n1 * OBS;
        #pragma unroll
        for (int kt = 0; kt < 4; kt++) {
            uint32_t aH[4], aL[4];
            #pragma unroll
            for (int q = 0; q < 2; q++) {
                const int k = kt * 16 + tid * 2 + q * 8;
                float2 v0 = *(const float2*)(r0p + k);
                float2 v1 = *(const float2*)(r1p + k);
                uint32_t h0 = cvt_bf16x2(v0.y, v0.x);
                aH[q*2]   = h0;
                aL[q*2]   = cvt_bf16x2(v0.y - hi_f(h0), v0.x - lo_f(h0));
                uint32_t h1 = cvt_bf16x2(v1.y, v1.x);
                aH[q*2+1] = h1;
                aL[q*2+1] = cvt_bf16x2(v1.y - hi_f(h1), v1.x - lo_f(h1));
            }
            #pragma unroll
            for (int j = 0; j < 16; j++) {
                uint4 B = g_Bemb[(kt * 16 + j) * 32 + lane];
                mma_bf16(xr0[2*j], xr0[2*j+1], xr1[2*j], xr1[2*j+1],
                         aH[0], aH[1], aH[2], aH[3], B.x, B.y);   // hiA*hiB
                mma_bf16(xr0[2*j], xr0[2*j+1], xr1[2*j], xr1[2*j+1],
                         aL[0], aL[1], aL[2], aL[3], B.x, B.y);   // loA*hiB
                mma_bf16(xr0[2*j], xr0[2*j+1], xr1[2*j], xr1[2*j+1],
                         aH[0], aH[1], aH[2], aH[3], B.z, B.w);   // hiA*loB
            }
        }
    }

    // ---- GCN layers (agg == per-graph mean: deg 16, norm 1/16) ----
    #pragma unroll
    for (int l = 0; l < 2; l++) {
        // xbar: warp-local reduce over 16 nodes; split hi/lo; pack into s_xp
        {
            float s[32];
            #pragma unroll
            for (int c = 0; c < 32; c++) s[c] = xr0[c] + xr1[c];
            #pragma unroll
            for (int off = 4; off <= 16; off <<= 1)
                #pragma unroll
                for (int c = 0; c < 32; c++)
                    s[c] += __shfl_xor_sync(0xffffffffu, s[c], off);
            #pragma unroll
            for (int e = 0; e < 2; e++) {
                const int j = 2 * g + e;
                float v0 = s[2*j] * 0.0625f, v1 = s[2*j+1] * 0.0625f;
                uint32_t hp = cvt_bf16x2(v1, v0);
                uint32_t lp = cvt_bf16x2(v1 - hi_f(hp), v0 - lo_f(hp));
                s_xp[w * 68 + 4 * j + tid]       = hp;
                s_xp[(w + 4) * 68 + 4 * j + tid] = lp;
            }
        }
        __syncthreads();

        // matvec via HMMA: A rows 0-3 = hi-xbar, rows 4-7 = lo-xbar
        // warp w computes jtiles 4w..4w+3 for all 4 graphs
        {
            float c1r[4][2], c2r[4][2];
            #pragma unroll
            for (int jj = 0; jj < 4; jj++) {
                c1r[jj][0] = c1r[jj][1] = 0.f;
                c2r[jj][0] = c2r[jj][1] = 0.f;
            }
            const uint4* WB = g_Wf + l * 4096;
            #pragma unroll
            for (int kt = 0; kt < 8; kt++) {
                uint32_t a0 = s_xp[g * 68 + 8 * kt + tid];
                uint32_t a2 = s_xp[g * 68 + 8 * kt + 4 + tid];
                #pragma unroll
                for (int jj = 0; jj < 4; jj++) {
                    const int j = w * 4 + jj;
                    uint4 B = WB[(kt * 16 + j) * 32 + lane];
                    float d2 = 0.f, d3 = 0.f;
                    mma_bf16(c1r[jj][0], c1r[jj][1], d2, d3,
                             a0, 0u, a2, 0u, B.x, B.y);     // hi+lo rows vs hiB
                    mma_bf16(c2r[jj][0], c2r[jj][1], d2, d3,
                             a0, 0u, a2, 0u, B.z, B.w);     // rows vs loB (lo·lo negligible)
                }
            }
            #pragma unroll
            for (int jj = 0; jj < 4; jj++) {
                float t0 = c1r[jj][0] + c2r[jj][0];
                float t1 = c1r[jj][1] + c2r[jj][1];
                t0 += __shfl_xor_sync(0xffffffffu, t0, 16);   // add lo-row partials
                t1 += __shfl_xor_sync(0xffffffffu, t1, 16);
                if (g < 4)
                    *(float2*)(s_m + g * 136 + 8 * (w * 4 + jj) + 2 * tid) =
                        make_float2(t0, t1);
            }
        }
        __syncthreads();

        // x = tanh(x + m[graph] + b_gcn)
        #pragma unroll
        for (int j = 0; j < 16; j++) {
            float2 mg = *(const float2*)(s_m + w * 136 + 8 * j + 2 * tid);
            float2 bg = *(const float2*)(b_gcn + l * HID + 8 * j + 2 * tid);
            const float a0 = mg.x + bg.x, a1 = mg.y + bg.y;
            xr0[2*j]   = htanh(xr0[2*j]   + a0);
            xr0[2*j+1] = htanh(xr0[2*j+1] + a1);
            xr1[2*j]   = htanh(xr1[2*j]   + a0);
            xr1[2*j+1] = htanh(xr1[2*j+1] + a1);
        }
        if (l == 0) __syncthreads();
    }

    // ---- head: out[graph] = mean_{16 nodes}(x . w_fc1) + b ----
    {
        float p = 0.f;
        #pragma unroll
        for (int j = 0; j < 16; j++) {
            float2 wf = *(const float2*)(w_fc1 + 8 * j + 2 * tid);
            p += (xr0[2*j]   + xr1[2*j])   * wf.x;
            p += (xr0[2*j+1] + xr1[2*j+1]) * wf.y;
        }
        #pragma unroll
        for (int off = 16; off; off >>= 1)
            p += __shfl_xor_sync(0xffffffffu, p, off);
        if (lane == 0)
            out[blockIdx.x * 4 + w] = p * 0.0625f + b_fc1[0];
    }
}

extern "C" void kernel_launch(void* const* d_in, const int* in_sizes, int n_in,
                              void* d_out, int out_size) {
    const float* cent_obs = (const float*)d_in[0];
    const float* w_emb    = (const float*)d_in[1];
    const float* b_emb    = (const float*)d_in[2];
    const float* w_gcn    = (const float*)d_in[3];
    const float* b_gcn    = (const float*)d_in[4];
    const float* w_fc1    = (const float*)d_in[5];
    const float* b_fc1    = (const float*)d_in[6];
    // edge_src/edge_dst: fixed complete graph -> per-graph mean; unused.
    float* out = (float*)d_out;

    prep_kernel<<<80, 128>>>(w_emb, w_gcn);

    const int blocks = out_size / 4;   // 2048
    gcn_critic_kernel<<<blocks, 128>>>(
        cent_obs, b_emb, b_gcn, w_fc1, b_fc1, out);
}

// round 9
// speedup vs baseline: 1.4143x; 1.1759x over previous
#include <cuda_runtime.h>
#include <cuda_bf16.h>
#include <stdint.h>

#define HID  128
#define OBS  64

// pre-packed MMA B-fragments, uint4 = {b0_hi, b1_hi, b0_lo, b1_lo}
__device__ __align__(16) uint4 g_Bemb[2048];   // [(kt*16+j)*32+lane], kt 0..3
__device__ __align__(16) uint4 g_Wf[8192];     // [l*4096 + (kt*16+j)*32+lane], kt 0..7

__device__ __forceinline__ uint32_t bf16_hi_bits(float v) {
    return (uint32_t)__bfloat16_as_ushort(__float2bfloat16(v));
}
__device__ __forceinline__ uint32_t cvt_bf16x2(float hi_elt, float lo_elt) {
    uint32_t r;
    asm("cvt.rn.bf16x2.f32 %0, %1, %2;" : "=r"(r) : "f"(hi_elt), "f"(lo_elt));
    return r;   // [31:16]=bf16(hi_elt), [15:0]=bf16(lo_elt)
}
__device__ __forceinline__ float lo_f(uint32_t u) { return __uint_as_float(u << 16); }
__device__ __forceinline__ float hi_f(uint32_t u) { return __uint_as_float(u & 0xffff0000u); }
__device__ __forceinline__ float htanh(float x) {
    float y; asm("tanh.approx.f32 %0, %1;" : "=f"(y) : "f"(x)); return y;
}
__device__ __forceinline__ void mma_bf16(float& c0, float& c1, float& c2, float& c3,
                                         uint32_t a0, uint32_t a1, uint32_t a2, uint32_t a3,
                                         uint32_t b0, uint32_t b1) {
    asm volatile(
        "mma.sync.aligned.m16n8k16.row.col.f32.bf16.bf16.f32 "
        "{%0,%1,%2,%3}, {%4,%5,%6,%7}, {%8,%9}, {%0,%1,%2,%3};"
        : "+f"(c0), "+f"(c1), "+f"(c2), "+f"(c3)
        : "r"(a0), "r"(a1), "r"(a2), "r"(a3), "r"(b0), "r"(b1));
}

// ---- prep: pack w_emb / w_gcn into uint4 B-fragments (hi/lo split bf16) ----
__global__ void prep_kernel(const float* __restrict__ w_emb,
                            const float* __restrict__ w_gcn) {
    if (blockIdx.x < 16) {
        int idx  = blockIdx.x * 128 + threadIdx.x;   // 0..2047
        int lane = idx & 31;
        int j    = (idx >> 5) & 15;
        int kt   = idx >> 9;                          // 0..3
        int g    = lane >> 2, tid = lane & 3;
        int n    = j * 8 + g;
        uint32_t hv[2], lv[2];
        #pragma unroll
        for (int p = 0; p < 2; p++) {
            int k0 = kt * 16 + tid * 2 + p * 8;
            float v0 = w_emb[k0 * HID + n];
            float v1 = w_emb[(k0 + 1) * HID + n];
            uint32_t h0 = bf16_hi_bits(v0), h1 = bf16_hi_bits(v1);
            uint32_t l0 = bf16_hi_bits(v0 - __uint_as_float(h0 << 16));
            uint32_t l1 = bf16_hi_bits(v1 - __uint_as_float(h1 << 16));
            hv[p] = (h1 << 16) | h0;
            lv[p] = (l1 << 16) | l0;
        }
        g_Bemb[(kt * 16 + j) * 32 + lane] = make_uint4(hv[0], hv[1], lv[0], lv[1]);
    } else {
        int idx  = (blockIdx.x - 16) * 128 + threadIdx.x;   // 0..8191
        int lane = idx & 31;
        int j    = (idx >> 5) & 15;
        int kt   = (idx >> 9) & 7;                          // 0..7
        int l    = idx >> 12;                               // 0..1
        int g    = lane >> 2, tid = lane & 3;
        int n    = j * 8 + g;
        uint32_t hv[2], lv[2];
        #pragma unroll
        for (int p = 0; p < 2; p++) {
            int k0 = kt * 16 + tid * 2 + p * 8;
            float v0 = w_gcn[l * HID * HID + k0 * HID + n];
            float v1 = w_gcn[l * HID * HID + (k0 + 1) * HID + n];
            uint32_t h0 = bf16_hi_bits(v0), h1 = bf16_hi_bits(v1);
            uint32_t l0 = bf16_hi_bits(v0 - __uint_as_float(h0 << 16));
            uint32_t l1 = bf16_hi_bits(v1 - __uint_as_float(h1 << 16));
            hv[p] = (h1 << 16) | h0;
            lv[p] = (l1 << 16) | l0;
        }
        g_Wf[l * 4096 + (kt * 16 + j) * 32 + lane] = make_uint4(hv[0], hv[1], lv[0], lv[1]);
    }
}

// block = 256 thr = 8 warps = 8 graphs (warp == graph)
// s_xp[16][68] u32: rows 0-7 hi-xbar graphs 0-7, rows 8-15 lo-xbar
// s_m [8][136] f32
__global__ __launch_bounds__(256, 2)
void gcn_critic_kernel(const float* __restrict__ cent_obs,
                       const float* __restrict__ b_emb,
                       const float* __restrict__ b_gcn,
                       const float* __restrict__ w_fc1,
                       const float* __restrict__ b_fc1,
                       float* __restrict__ out)
{
    __shared__ uint32_t s_xp[16 * 68];
    __shared__ float    s_m[8 * 136];

    const int t    = threadIdx.x;
    const int w    = t >> 5;            // warp == local graph 0..7
    const int lane = t & 31;
    const int g    = lane >> 2;
    const int tid  = lane & 3;

    const long n0 = (long)blockIdx.x * 128 + w * 16 + g;
    const long n1 = n0 + 8;

    // ---- embedding GEMM, kt-outer (only one kt's A fragments live) ----
    float xr0[32], xr1[32];
    {
        #pragma unroll
        for (int j = 0; j < 16; j++) {
            float2 be = *(const float2*)(b_emb + 8 * j + 2 * tid);
            xr0[2*j] = be.x; xr0[2*j+1] = be.y;
            xr1[2*j] = be.x; xr1[2*j+1] = be.y;
        }
        const float* r0p = cent_obs + n0 * OBS;
        const float* r1p = cent_obs + n1 * OBS;
        #pragma unroll
        for (int kt = 0; kt < 4; kt++) {
            uint32_t aH[4], aL[4];
            #pragma unroll
            for (int q = 0; q < 2; q++) {
                const int k = kt * 16 + tid * 2 + q * 8;
                float2 v0 = *(const float2*)(r0p + k);
                float2 v1 = *(const float2*)(r1p + k);
                uint32_t h0 = cvt_bf16x2(v0.y, v0.x);
                aH[q*2]   = h0;
                aL[q*2]   = cvt_bf16x2(v0.y - hi_f(h0), v0.x - lo_f(h0));
                uint32_t h1 = cvt_bf16x2(v1.y, v1.x);
                aH[q*2+1] = h1;
                aL[q*2+1] = cvt_bf16x2(v1.y - hi_f(h1), v1.x - lo_f(h1));
            }
            #pragma unroll
            for (int j = 0; j < 16; j++) {
                uint4 B = g_Bemb[(kt * 16 + j) * 32 + lane];
                mma_bf16(xr0[2*j], xr0[2*j+1], xr1[2*j], xr1[2*j+1],
                         aH[0], aH[1], aH[2], aH[3], B.x, B.y);   // hiA*hiB
                mma_bf16(xr0[2*j], xr0[2*j+1], xr1[2*j], xr1[2*j+1],
                         aL[0], aL[1], aL[2], aL[3], B.x, B.y);   // loA*hiB
                mma_bf16(xr0[2*j], xr0[2*j+1], xr1[2*j], xr1[2*j+1],
                         aH[0], aH[1], aH[2], aH[3], B.z, B.w);   // hiA*loB
            }
        }
    }

    // ---- GCN layers (agg == per-graph mean: deg 16, norm 1/16) ----
    #pragma unroll
    for (int l = 0; l < 2; l++) {
        // xbar: ownership-splitting butterfly over lane bits 2,3,4 (g-axis).
        // Final: lane (g,tid) holds f[e'] = sum over 16 nodes of s[4g+e'].
        {
            float s[32];
            #pragma unroll
            for (int c = 0; c < 32; c++) s[c] = xr0[c] + xr1[c];

            const bool b2 = (lane & 4)  != 0;
            const bool b3 = (lane & 8)  != 0;
            const bool b4 = (lane & 16) != 0;

            float r[16];   // stage 1 (xor 4): keep cols with bit2(col)==b2
            #pragma unroll
            for (int i = 0; i < 16; i++) {
                const int c0 = ((i >> 2) << 3) | (i & 3);
                const int c1 = c0 | 4;
                float keep = b2 ? s[c1] : s[c0];
                float send = b2 ? s[c0] : s[c1];
                r[i] = keep + __shfl_xor_sync(0xffffffffu, send, 4);
            }
            float q[8];    // stage 2 (xor 8): split on next col bit
            #pragma unroll
            for (int i = 0; i < 8; i++) {
                const int c0 = ((i >> 2) << 3) | (i & 3);
                const int c1 = c0 | 4;
                float keep = b3 ? r[c1] : r[c0];
                float send = b3 ? r[c0] : r[c1];
                q[i] = keep + __shfl_xor_sync(0xffffffffu, send, 8);
            }
            float f[4];    // stage 3 (xor 16)
            #pragma unroll
            for (int e = 0; e < 4; e++) {
                float keep = b4 ? q[e | 4] : q[e];
                float send = b4 ? q[e] : q[e | 4];
                f[e] = keep + __shfl_xor_sync(0xffffffffu, send, 16);
            }
            // lane (g,tid) stores col-pairs of j = 2g+e: values f[2e], f[2e+1]
            #pragma unroll
            for (int e = 0; e < 2; e++) {
                const int j = 2 * g + e;
                float v0 = f[2*e]   * 0.0625f;
                float v1 = f[2*e+1] * 0.0625f;
                uint32_t hp = cvt_bf16x2(v1, v0);
                uint32_t lp = cvt_bf16x2(v1 - hi_f(hp), v0 - lo_f(hp));
                s_xp[w * 68 + 4 * j + tid]       = hp;   // hi row w
                s_xp[(w + 8) * 68 + 4 * j + tid] = lp;   // lo row w+8
            }
        }
        __syncthreads();

        // matvec via HMMA, full 16-row A: rows 0-7 hi-xbar, rows 8-15 lo-xbar.
        // warp w -> j-tiles 2w, 2w+1. Lane owns graph g's hi (c0,c1) + lo (c2,c3).
        {
            float acc[2][4];
            #pragma unroll
            for (int jj = 0; jj < 2; jj++)
                acc[jj][0] = acc[jj][1] = acc[jj][2] = acc[jj][3] = 0.f;

            const uint4* WB = g_Wf + l * 4096;
            #pragma unroll
            for (int kt = 0; kt < 8; kt++) {
                uint32_t a0 = s_xp[g * 68 + 8 * kt + tid];            // hi, k lo-half
                uint32_t a1 = s_xp[(g + 8) * 68 + 8 * kt + tid];      // lo, k lo-half
                uint32_t a2 = s_xp[g * 68 + 8 * kt + 4 + tid];        // hi, k hi-half
                uint32_t a3 = s_xp[(g + 8) * 68 + 8 * kt + 4 + tid];  // lo, k hi-half
                #pragma unroll
                for (int jj = 0; jj < 2; jj++) {
                    const int j = 2 * w + jj;
                    uint4 B = WB[(kt * 16 + j) * 32 + lane];
                    mma_bf16(acc[jj][0], acc[jj][1], acc[jj][2], acc[jj][3],
                             a0, a1, a2, a3, B.x, B.y);   // hi&lo rows vs hiB
                    mma_bf16(acc[jj][0], acc[jj][1], acc[jj][2], acc[jj][3],
                             a0, 0u, a2, 0u, B.z, B.w);   // hi rows vs loB
                }
            }
            #pragma unroll
            for (int jj = 0; jj < 2; jj++) {
                const int j = 2 * w + jj;
                *(float2*)(s_m + g * 136 + 8 * j + 2 * tid) =
                    make_float2(acc[jj][0] + acc[jj][2],    // hi + lo row parts
                                acc[jj][1] + acc[jj][3]);
            }
        }
        __syncthreads();

        // x = tanh(x + m[graph] + b_gcn)
        #pragma unroll
        for (int j = 0; j < 16; j++) {
            float2 mg = *(const float2*)(s_m + w * 136 + 8 * j + 2 * tid);
            float2 bg = *(const float2*)(b_gcn + l * HID + 8 * j + 2 * tid);
            const float a0 = mg.x + bg.x, a1 = mg.y + bg.y;
            xr0[2*j]   = htanh(xr0[2*j]   + a0);
            xr0[2*j+1] = htanh(xr0[2*j+1] + a1);
            xr1[2*j]   = htanh(xr1[2*j]   + a0);
            xr1[2*j+1] = htanh(xr1[2*j+1] + a1);
        }
        if (l == 0) __syncthreads();
    }

    // ---- head: out[graph] = mean_{16 nodes}(x . w_fc1) + b ----
    {
        float p = 0.f;
        #pragma unroll
        for (int j = 0; j < 16; j++) {
            float2 wf = *(const float2*)(w_fc1 + 8 * j + 2 * tid);
            p += (xr0[2*j]   + xr1[2*j])   * wf.x;
            p += (xr0[2*j+1] + xr1[2*j+1]) * wf.y;
        }
        #pragma unroll
        for (int off = 16; off; off >>= 1)
            p += __shfl_xor_sync(0xffffffffu, p, off);
        if (lane == 0)
            out[blockIdx.x * 8 + w] = p * 0.0625f + b_fc1[0];
    }
}

extern "C" void kernel_launch(void* const* d_in, const int* in_sizes, int n_in,
                              void* d_out, int out_size) {
    const float* cent_obs = (const float*)d_in[0];
    const float* w_emb    = (const float*)d_in[1];
    const float* b_emb    = (const float*)d_in[2];
    const float* w_gcn    = (const float*)d_in[3];
    const float* b_gcn    = (const float*)d_in[4];
    const float* w_fc1    = (const float*)d_in[5];
    const float* b_fc1    = (const float*)d_in[6];
    // edge_src/edge_dst: fixed complete graph -> per-graph mean; unused.
    float* out = (float*)d_out;

    prep_kernel<<<80, 128>>>(w_emb, w_gcn);

    const int blocks = out_size / 8;   // 1024
    gcn_critic_kernel<<<blocks, 256>>>(
        cent_obs, b_emb, b_gcn, w_fc1, b_fc1, out);
}

// round 10
// speedup vs baseline: 1.5488x; 1.0951x over previous
#include <cuda_runtime.h>
#include <cuda_bf16.h>
#include <stdint.h>

#define HID  128
#define OBS  64

// pre-packed MMA B-fragments, uint4 = {b0_hi, b1_hi, b0_lo, b1_lo}
__device__ __align__(16) uint4 g_Bemb[2048];   // [(kt*16+j)*32+lane], kt 0..3
__device__ __align__(16) uint4 g_Wf[8192];     // [l*4096 + (kt*16+j)*32+lane], kt 0..7

__device__ __forceinline__ uint32_t bf16_hi_bits(float v) {
    return (uint32_t)__bfloat16_as_ushort(__float2bfloat16(v));
}
__device__ __forceinline__ uint32_t cvt_bf16x2(float hi_elt, float lo_elt) {
    uint32_t r;
    asm("cvt.rn.bf16x2.f32 %0, %1, %2;" : "=r"(r) : "f"(hi_elt), "f"(lo_elt));
    return r;   // [31:16]=bf16(hi_elt), [15:0]=bf16(lo_elt)
}
__device__ __forceinline__ float lo_f(uint32_t u) { return __uint_as_float(u << 16); }
__device__ __forceinline__ float hi_f(uint32_t u) { return __uint_as_float(u & 0xffff0000u); }
__device__ __forceinline__ float htanh(float x) {
    float y; asm("tanh.approx.f32 %0, %1;" : "=f"(y) : "f"(x)); return y;
}
__device__ __forceinline__ void mma_bf16(float& c0, float& c1, float& c2, float& c3,
                                         uint32_t a0, uint32_t a1, uint32_t a2, uint32_t a3,
                                         uint32_t b0, uint32_t b1) {
    asm volatile(
        "mma.sync.aligned.m16n8k16.row.col.f32.bf16.bf16.f32 "
        "{%0,%1,%2,%3}, {%4,%5,%6,%7}, {%8,%9}, {%0,%1,%2,%3};"
        : "+f"(c0), "+f"(c1), "+f"(c2), "+f"(c3)
        : "r"(a0), "r"(a1), "r"(a2), "r"(a3), "r"(b0), "r"(b1));
}

// ---- prep: pack w_emb / w_gcn into uint4 B-fragments (hi/lo split bf16) ----
__global__ void prep_kernel(const float* __restrict__ w_emb,
                            const float* __restrict__ w_gcn) {
    if (blockIdx.x < 16) {
        int idx  = blockIdx.x * 128 + threadIdx.x;   // 0..2047
        int lane = idx & 31;
        int j    = (idx >> 5) & 15;
        int kt   = idx >> 9;                          // 0..3
        int g    = lane >> 2, tid = lane & 3;
        int n    = j * 8 + g;
        uint32_t hv[2], lv[2];
        #pragma unroll
        for (int p = 0; p < 2; p++) {
            int k0 = kt * 16 + tid * 2 + p * 8;
            float v0 = w_emb[k0 * HID + n];
            float v1 = w_emb[(k0 + 1) * HID + n];
            uint32_t h0 = bf16_hi_bits(v0), h1 = bf16_hi_bits(v1);
            uint32_t l0 = bf16_hi_bits(v0 - __uint_as_float(h0 << 16));
            uint32_t l1 = bf16_hi_bits(v1 - __uint_as_float(h1 << 16));
            hv[p] = (h1 << 16) | h0;
            lv[p] = (l1 << 16) | l0;
        }
        g_Bemb[(kt * 16 + j) * 32 + lane] = make_uint4(hv[0], hv[1], lv[0], lv[1]);
    } else {
        int idx  = (blockIdx.x - 16) * 128 + threadIdx.x;   // 0..8191
        int lane = idx & 31;
        int j    = (idx >> 5) & 15;
        int kt   = (idx >> 9) & 7;                          // 0..7
        int l    = idx >> 12;                               // 0..1
        int g    = lane >> 2, tid = lane & 3;
        int n    = j * 8 + g;
        uint32_t hv[2], lv[2];
        #pragma unroll
        for (int p = 0; p < 2; p++) {
            int k0 = kt * 16 + tid * 2 + p * 8;
            float v0 = w_gcn[l * HID * HID + k0 * HID + n];
            float v1 = w_gcn[l * HID * HID + (k0 + 1) * HID + n];
            uint32_t h0 = bf16_hi_bits(v0), h1 = bf16_hi_bits(v1);
            uint32_t l0 = bf16_hi_bits(v0 - __uint_as_float(h0 << 16));
            uint32_t l1 = bf16_hi_bits(v1 - __uint_as_float(h1 << 16));
            hv[p] = (h1 << 16) | h0;
            lv[p] = (l1 << 16) | l0;
        }
        g_Wf[l * 4096 + (kt * 16 + j) * 32 + lane] = make_uint4(hv[0], hv[1], lv[0], lv[1]);
    }
}

// block = 256 thr = 8 warps; 8 graphs per block.
// Warp w: graph pair p = w&3 -> graphs (2p, 2p+1); j-half h = w>>2 (j = h*8 + jj).
// Each B-fragment load serves BOTH graphs (halves embedding L1 traffic).
// s_xp[16][68] u32: rows 0-7 hi-xbar graphs 0-7, rows 8-15 lo-xbar
// s_m [8][136] f32 ; s_red[16]
__global__ __launch_bounds__(256, 2)
void gcn_critic_kernel(const float* __restrict__ cent_obs,
                       const float* __restrict__ b_emb,
                       const float* __restrict__ b_gcn,
                       const float* __restrict__ w_fc1,
                       const float* __restrict__ b_fc1,
                       float* __restrict__ out)
{
    __shared__ uint32_t s_xp[16 * 68];
    __shared__ float    s_m[8 * 136];
    __shared__ float    s_red[16];

    const int t    = threadIdx.x;
    const int w    = t >> 5;
    const int lane = t & 31;
    const int g    = lane >> 2;
    const int tid  = lane & 3;
    const int p    = w & 3;            // graph pair
    const int h    = w >> 2;           // j-half
    const int gA   = 2 * p;            // local graphs
    const int gB   = 2 * p + 1;

    const int base = blockIdx.x * 128;
    const float* rA0 = cent_obs + (base + gA * 16 + g) * OBS;
    const float* rA1 = rA0 + 8 * OBS;
    const float* rB0 = cent_obs + (base + gB * 16 + g) * OBS;
    const float* rB1 = rB0 + 8 * OBS;

    // ---- embedding GEMM, kt-outer; one B load feeds both graphs ----
    float xA0[16], xA1[16], xB0[16], xB1[16];
    {
        #pragma unroll
        for (int jj = 0; jj < 8; jj++) {
            float2 be = *(const float2*)(b_emb + (h * 8 + jj) * 8 + 2 * tid);
            xA0[2*jj] = be.x; xA0[2*jj+1] = be.y;
            xA1[2*jj] = be.x; xA1[2*jj+1] = be.y;
            xB0[2*jj] = be.x; xB0[2*jj+1] = be.y;
            xB1[2*jj] = be.x; xB1[2*jj+1] = be.y;
        }
        #pragma unroll
        for (int kt = 0; kt < 4; kt++) {
            uint32_t aHA[4], aLA[4], aHB[4], aLB[4];
            #pragma unroll
            for (int q = 0; q < 2; q++) {
                const int k = kt * 16 + tid * 2 + q * 8;
                float2 v;
                uint32_t hh;
                v = *(const float2*)(rA0 + k);
                hh = cvt_bf16x2(v.y, v.x);
                aHA[q*2]   = hh;
                aLA[q*2]   = cvt_bf16x2(v.y - hi_f(hh), v.x - lo_f(hh));
                v = *(const float2*)(rA1 + k);
                hh = cvt_bf16x2(v.y, v.x);
                aHA[q*2+1] = hh;
                aLA[q*2+1] = cvt_bf16x2(v.y - hi_f(hh), v.x - lo_f(hh));
                v = *(const float2*)(rB0 + k);
                hh = cvt_bf16x2(v.y, v.x);
                aHB[q*2]   = hh;
                aLB[q*2]   = cvt_bf16x2(v.y - hi_f(hh), v.x - lo_f(hh));
                v = *(const float2*)(rB1 + k);
                hh = cvt_bf16x2(v.y, v.x);
                aHB[q*2+1] = hh;
                aLB[q*2+1] = cvt_bf16x2(v.y - hi_f(hh), v.x - lo_f(hh));
            }
            #pragma unroll
            for (int jj = 0; jj < 8; jj++) {
                const int j = h * 8 + jj;
                uint4 B = g_Bemb[(kt * 16 + j) * 32 + lane];
                mma_bf16(xA0[2*jj], xA0[2*jj+1], xA1[2*jj], xA1[2*jj+1],
                         aHA[0], aHA[1], aHA[2], aHA[3], B.x, B.y);
                mma_bf16(xA0[2*jj], xA0[2*jj+1], xA1[2*jj], xA1[2*jj+1],
                         aLA[0], aLA[1], aLA[2], aLA[3], B.x, B.y);
                mma_bf16(xA0[2*jj], xA0[2*jj+1], xA1[2*jj], xA1[2*jj+1],
                         aHA[0], aHA[1], aHA[2], aHA[3], B.z, B.w);
                mma_bf16(xB0[2*jj], xB0[2*jj+1], xB1[2*jj], xB1[2*jj+1],
                         aHB[0], aHB[1], aHB[2], aHB[3], B.x, B.y);
                mma_bf16(xB0[2*jj], xB0[2*jj+1], xB1[2*jj], xB1[2*jj+1],
                         aLB[0], aLB[1], aLB[2], aLB[3], B.x, B.y);
                mma_bf16(xB0[2*jj], xB0[2*jj+1], xB1[2*jj], xB1[2*jj+1],
                         aHB[0], aHB[1], aHB[2], aHB[3], B.z, B.w);
            }
        }
    }

    const bool b2 = (lane & 4)  != 0;
    const bool b3 = (lane & 8)  != 0;
    const bool b4 = (lane & 16) != 0;

    // ---- GCN layers (agg == per-graph mean: deg 16, norm 1/16) ----
    #pragma unroll
    for (int l = 0; l < 2; l++) {
        // xbar for both graphs: ownership-splitting butterfly over jj bits.
        // Final: lane (g,tid) owns jj = g, holds f[0..1] = col-pair sums.
        #pragma unroll
        for (int gi = 0; gi < 2; gi++) {
            const float* x0 = gi ? xB0 : xA0;
            const float* x1 = gi ? xB1 : xA1;
            const int row = gi ? gB : gA;

            float s[16];
            #pragma unroll
            for (int c = 0; c < 16; c++) s[c] = x0[c] + x1[c];

            float r[8];   // stage 1 (xor 4): keep jj bit0 == b2
            #pragma unroll
            for (int i = 0; i < 8; i++) {
                const int jj2 = i >> 1, e = i & 1;
                const int c0 = ((jj2 << 1) | 0) * 2 + e;
                const int c1 = ((jj2 << 1) | 1) * 2 + e;
                float keep = b2 ? s[c1] : s[c0];
                float send = b2 ? s[c0] : s[c1];
                r[i] = keep + __shfl_xor_sync(0xffffffffu, send, 4);
            }
            float q[4];   // stage 2 (xor 8): keep jj bit1 == b3
            #pragma unroll
            for (int i = 0; i < 4; i++) {
                const int jj3 = i >> 1, e = i & 1;
                const int c0 = ((jj3 << 1) | 0) * 2 + e;
                const int c1 = ((jj3 << 1) | 1) * 2 + e;
                float keep = b3 ? r[c1] : r[c0];
                float send = b3 ? r[c0] : r[c1];
                q[i] = keep + __shfl_xor_sync(0xffffffffu, send, 8);
            }
            float f[2];   // stage 3 (xor 16): keep jj bit2 == b4
            #pragma unroll
            for (int e = 0; e < 2; e++) {
                float keep = b4 ? q[2 + e] : q[e];
                float send = b4 ? q[e] : q[2 + e];
                f[e] = keep + __shfl_xor_sync(0xffffffffu, send, 16);
            }
            // owned jj == g ; store col-pair of j = h*8+g
            const int j = h * 8 + g;
            float v0 = f[0] * 0.0625f, v1 = f[1] * 0.0625f;
            uint32_t hp = cvt_bf16x2(v1, v0);
            uint32_t lp = cvt_bf16x2(v1 - hi_f(hp), v0 - lo_f(hp));
            s_xp[row * 68 + 4 * j + tid]       = hp;   // hi row
            s_xp[(row + 8) * 68 + 4 * j + tid] = lp;   // lo row
        }
        __syncthreads();

        // matvec via HMMA, full 16-row A: rows 0-7 hi-xbar, rows 8-15 lo-xbar.
        // warp w -> j-tiles 2w, 2w+1. Lane owns graph g's hi (c0,c1) + lo (c2,c3).
        {
            float acc[2][4];
            #pragma unroll
            for (int jj = 0; jj < 2; jj++)
                acc[jj][0] = acc[jj][1] = acc[jj][2] = acc[jj][3] = 0.f;

            const uint4* WB = g_Wf + l * 4096;
            #pragma unroll
            for (int kt = 0; kt < 8; kt++) {
                uint32_t a0 = s_xp[g * 68 + 8 * kt + tid];
                uint32_t a1 = s_xp[(g + 8) * 68 + 8 * kt + tid];
                uint32_t a2 = s_xp[g * 68 + 8 * kt + 4 + tid];
                uint32_t a3 = s_xp[(g + 8) * 68 + 8 * kt + 4 + tid];
                #pragma unroll
                for (int jj = 0; jj < 2; jj++) {
                    const int j = 2 * w + jj;
                    uint4 B = WB[(kt * 16 + j) * 32 + lane];
                    mma_bf16(acc[jj][0], acc[jj][1], acc[jj][2], acc[jj][3],
                             a0, a1, a2, a3, B.x, B.y);   // hi&lo rows vs hiB
                    mma_bf16(acc[jj][0], acc[jj][1], acc[jj][2], acc[jj][3],
                             a0, 0u, a2, 0u, B.z, B.w);   // hi rows vs loB
                }
            }
            #pragma unroll
            for (int jj = 0; jj < 2; jj++) {
                const int j = 2 * w + jj;
                *(float2*)(s_m + g * 136 + 8 * j + 2 * tid) =
                    make_float2(acc[jj][0] + acc[jj][2],
                                acc[jj][1] + acc[jj][3]);
            }
        }
        __syncthreads();

        // x = tanh(x + m[graph] + b_gcn) for both graphs, this j-half
        #pragma unroll
        for (int jj = 0; jj < 8; jj++) {
            const int j = h * 8 + jj;
            float2 bg = *(const float2*)(b_gcn + l * HID + 8 * j + 2 * tid);
            float2 mA = *(const float2*)(s_m + gA * 136 + 8 * j + 2 * tid);
            float2 mB = *(const float2*)(s_m + gB * 136 + 8 * j + 2 * tid);
            const float aA0 = mA.x + bg.x, aA1 = mA.y + bg.y;
            const float aB0 = mB.x + bg.x, aB1 = mB.y + bg.y;
            xA0[2*jj]   = htanh(xA0[2*jj]   + aA0);
            xA0[2*jj+1] = htanh(xA0[2*jj+1] + aA1);
            xA1[2*jj]   = htanh(xA1[2*jj]   + aA0);
            xA1[2*jj+1] = htanh(xA1[2*jj+1] + aA1);
            xB0[2*jj]   = htanh(xB0[2*jj]   + aB0);
            xB0[2*jj+1] = htanh(xB0[2*jj+1] + aB1);
            xB1[2*jj]   = htanh(xB1[2*jj]   + aB0);
            xB1[2*jj+1] = htanh(xB1[2*jj+1] + aB1);
        }
        if (l == 0) __syncthreads();
    }

    // ---- head: partial dot over this warp's col-half, per graph ----
    {
        float pA = 0.f, pB = 0.f;
        #pragma unroll
        for (int jj = 0; jj < 8; jj++) {
            const int j = h * 8 + jj;
            float2 wf = *(const float2*)(w_fc1 + 8 * j + 2 * tid);
            pA += (xA0[2*jj]   + xA1[2*jj])   * wf.x;
            pA += (xA0[2*jj+1] + xA1[2*jj+1]) * wf.y;
            pB += (xB0[2*jj]   + xB1[2*jj])   * wf.x;
            pB += (xB0[2*jj+1] + xB1[2*jj+1]) * wf.y;
        }
        #pragma unroll
        for (int off = 16; off; off >>= 1) {
            pA += __shfl_xor_sync(0xffffffffu, pA, off);
            pB += __shfl_xor_sync(0xffffffffu, pB, off);
        }
        if (lane == 0) {
            s_red[gA * 2 + h] = pA;
            s_red[gB * 2 + h] = pB;
        }
    }
    __syncthreads();
    if (t < 8)
        out[blockIdx.x * 8 + t] =
            (s_red[2 * t] + s_red[2 * t + 1]) * 0.0625f + b_fc1[0];
}

extern "C" void kernel_launch(void* const* d_in, const int* in_sizes, int n_in,
                              void* d_out, int out_size) {
    const float* cent_obs = (const float*)d_in[0];
    const float* w_emb    = (const float*)d_in[1];
    const float* b_emb    = (const float*)d_in[2];
    const float* w_gcn    = (const float*)d_in[3];
    const float* b_gcn    = (const float*)d_in[4];
    const float* w_fc1    = (const float*)d_in[5];
    const float* b_fc1    = (const float*)d_in[6];
    // edge_src/edge_dst: fixed complete graph -> per-graph mean; unused.
    float* out = (float*)d_out;

    prep_kernel<<<80, 128>>>(w_emb, w_gcn);

    const int blocks = out_size / 8;   // 1024
    gcn_critic_kernel<<<blocks, 256>>>(
        cent_obs, b_emb, b_gcn, w_fc1, b_fc1, out);
}